// round 6
// baseline (speedup 1.0000x reference)
#include <cuda_runtime.h>

#define NTOT 200      // histogram bins
#define TILE 256      // tile side (A rows and B cols per block)
#define BLKT 128      // pair-kernel threads (2 A rows per thread)
#define NWARP 4
#define NBUCK 256     // x-sort buckets
#define SORTT 1024    // sort-kernel threads
#define MAXPTS 16384

// Sorted & prescaled points: (x,y,z)*real_size*20, w=|p|^2.
__device__ float4 g_pts[MAXPTS];
// 3 raw integer histograms: [0]=00-tri, [1]=01-cross, [2]=11-tri.
// Zeroed by the finishing block each run -> graph replays start clean.
__device__ int g_hist[3 * NTOT];
__device__ unsigned int g_done;   // block-completion ticket

__device__ __forceinline__ float fsqrt_approx(float x) {
    float r;
    asm("sqrt.approx.f32 %0, %1;" : "=f"(r) : "f"(x));
    return r;
}

// Counting sort by x-bucket; block 0 -> pos0, block 1 -> pos1. Within-bucket
// order is race-dependent, which is fine: the histogram is a permutation-
// invariant integer reduction.
__global__ __launch_bounds__(SORTT) void sort_kernel(
    const float* __restrict__ pos0, const float* __restrict__ pos1,
    const float* __restrict__ rs, int n0, int n1)
{
    __shared__ int cnt[NBUCK];
    __shared__ int offs[NBUCK];
    const float* p = blockIdx.x ? pos1 : pos0;
    const int n    = blockIdx.x ? n1 : n0;
    const int base = blockIdx.x ? n0 : 0;
    const int tid  = threadIdx.x;

    const float r0 = rs[0] * 20.0f, r1 = rs[1] * 20.0f, r2 = rs[2] * 20.0f;

    if (tid < NBUCK) cnt[tid] = 0;
    __syncthreads();
    for (int i = tid; i < n; i += SORTT) {
        int b = (int)(p[3 * i] * (float)NBUCK);
        b = max(0, min(NBUCK - 1, b));
        atomicAdd(&cnt[b], 1);
    }
    __syncthreads();
    int own = (tid < NBUCK) ? cnt[tid] : 0;
    // inclusive Hillis-Steele scan over NBUCK entries (all threads sync)
    for (int d = 1; d < NBUCK; d <<= 1) {
        int t = 0;
        if (tid < NBUCK && tid >= d) t = cnt[tid - d];
        __syncthreads();
        if (tid < NBUCK) cnt[tid] += t;
        __syncthreads();
    }
    if (tid < NBUCK) offs[tid] = cnt[tid] - own;   // exclusive start cursor
    __syncthreads();
    for (int i = tid; i < n; i += SORTT) {
        float x = p[3 * i + 0];
        float y = p[3 * i + 1];
        float z = p[3 * i + 2];
        int b = (int)(x * (float)NBUCK);
        b = max(0, min(NBUCK - 1, b));
        int pos = atomicAdd(&offs[b], 1);
        float sx = x * r0, sy = y * r1, sz = z * r2;
        float q = sx * sx; q = fmaf(sy, sy, q); q = fmaf(sz, sz, q);
        g_pts[base + pos] = make_float4(sx, sy, sz, q);
    }
}

// Invert upper-triangle linear index t -> (bi, bj), bj >= bi.
__device__ __forceinline__ void tri_decode(int t, int n, int& bi, int& bj) {
    float fn = (float)(2 * n + 1);
    int b = (int)((fn - sqrtf(fmaxf(fn * fn - 8.0f * (float)t, 0.0f))) * 0.5f);
    if (b < 0) b = 0;
    if (b > n - 1) b = n - 1;
    while (b > 0 && t < b * (2 * n - b + 1) / 2) b--;
    while (b < n - 1 && t >= (b + 1) * (2 * n - b) / 2) b++;
    bi = b;
    bj = b + (t - b * (2 * n - b + 1) / 2);
}

// Fused: all three pair regions in one grid; x-gap tile culling; the LAST
// block to finish runs the normalization epilogue (no separate kernel).
__global__ __launch_bounds__(BLKT) void pair_fused_kernel(
    const float* __restrict__ count_in, float* __restrict__ out,
    const float* __restrict__ rs,
    int n0, int n1, int nb0, int nb1, int T0, int C)
{
    __shared__ float4 sB[TILE];
    __shared__ int    sh[NWARP * NTOT];
    __shared__ bool   s_last;

    const int tid = threadIdx.x;

    // ---- decode block -> work unit ----
    int w = blockIdx.x;
    int bi, bj, aOff, bOff, nA, nB, histIdx;
    bool diag;
    if (w < T0) {                     // 0-0 triangle
        tri_decode(w, nb0, bi, bj);
        aOff = 0; bOff = 0; nA = n0; nB = n0; histIdx = 0;
        diag = (bi == bj);
    } else if (w < T0 + C) {          // 0-1 cross
        int u = w - T0;
        bi = u / nb1; bj = u - bi * nb1;
        aOff = 0; nA = n0; bOff = n0; nB = n1; histIdx = 1;
        diag = false;
    } else {                          // 1-1 triangle
        int u = w - T0 - C;
        tri_decode(u, nb1, bi, bj);
        aOff = n0; bOff = n0; nA = n1; nB = n1; histIdx = 2;
        diag = (bi == bj);
    }
    const int rowStart  = bi * TILE;
    const int chunkBase = bj * TILE;

    // ---- x-gap cull (bucket-granular sort: pad cutoff 200 -> 205) ----
    bool culled;
    {
        float a_lo = g_pts[aOff + rowStart].x;
        float a_hi = g_pts[aOff + min(rowStart + TILE - 1, nA - 1)].x;
        float b_lo = g_pts[bOff + chunkBase].x;
        float b_hi = g_pts[bOff + min(chunkBase + TILE - 1, nB - 1)].x;
        culled = fmaxf(b_lo - a_hi, a_lo - b_hi) > 205.0f;
    }

    if (!culled) {
        const int wid = tid >> 5;
        int* myh = &sh[wid * NTOT];

        #pragma unroll
        for (int idx = tid; idx < NWARP * NTOT; idx += BLKT) sh[idx] = 0;

        #pragma unroll
        for (int t = 0; t < 2; t++) {
            int k = tid + t * BLKT;
            int j = chunkBase + k;
            sB[k] = (j < nB) ? g_pts[bOff + j]
                             : make_float4(0.f, 0.f, 0.f, 1e30f);
        }

        float ax2[2], ay2[2], az2[2], aw[2];
        int   irow[2];
        #pragma unroll
        for (int t = 0; t < 2; t++) {
            int i = rowStart + tid + t * BLKT;
            irow[t] = i;
            float4 a = (i < nA) ? g_pts[aOff + i]
                                : make_float4(0.f, 0.f, 0.f, 1e30f);
            ax2[t] = -2.0f * a.x; ay2[t] = -2.0f * a.y;
            az2[t] = -2.0f * a.z; aw[t]  = a.w;
        }
        __syncthreads();

        if (diag) {
            #pragma unroll 4
            for (int k = 0; k < TILE; k++) {
                float4 b = sB[k];
                #pragma unroll
                for (int t = 0; t < 2; t++) {
                    float s = aw[t] + b.w;
                    s = fmaf(ax2[t], b.x, s);
                    s = fmaf(ay2[t], b.y, s);
                    s = fmaf(az2[t], b.z, s);
                    float d = fsqrt_approx(fmaxf(s, 0.0f));
                    if (d < (float)NTOT && (chunkBase + k) > irow[t])
                        atomicAdd(&myh[(int)d], 1);
                }
            }
        } else {
            #pragma unroll 4
            for (int k = 0; k < TILE; k++) {
                float4 b = sB[k];
                #pragma unroll
                for (int t = 0; t < 2; t++) {
                    float s = aw[t] + b.w;
                    s = fmaf(ax2[t], b.x, s);
                    s = fmaf(ay2[t], b.y, s);
                    s = fmaf(az2[t], b.z, s);
                    float d = fsqrt_approx(fmaxf(s, 0.0f));
                    if (d < (float)NTOT)
                        atomicAdd(&myh[(int)d], 1);
                }
            }
        }
        __syncthreads();

        for (int t = tid; t < NTOT; t += BLKT) {
            int v = sh[t] + sh[NTOT + t] + sh[2 * NTOT + t] + sh[3 * NTOT + t];
            if (v) atomicAdd(&g_hist[histIdx * NTOT + t], v);
        }
    }

    // ---- completion ticket; last block runs the normalization epilogue ----
    __syncthreads();
    if (tid == 0) {
        __threadfence();
        unsigned int v = atomicAdd(&g_done, 1u);
        s_last = (v == gridDim.x - 1);
    }
    __syncthreads();
    if (!s_last) return;
    __threadfence();

    for (int idx = tid; idx < 4 * NTOT; idx += BLKT) {
        int k  = idx % NTOT;
        int ij = idx / NTOT;                       // i*2 + j
        int hI = (ij == 0) ? 0 : ((ij == 3) ? 2 : 1);
        float mult = (ij == 0 || ij == 3) ? 2.0f : 1.0f;  // triangle -> full
        float na = (float)((ij >> 1) ? n1 : n0);
        float nb = (float)((ij & 1) ? n1 : n0);
        float vol = rs[0] * rs[1] * rs[2];

        float counts = (float)g_hist[hI * NTOT + k] * mult;
        double r = 0.025 + (double)k * 0.05;
        float sv = (float)(r * 0.05 * 2.0 * 3.14159265358979323846 * 3.0);
        float density = nb / vol;
        float res = counts / density / sv / na;   // same division order as ref
        out[idx] = count_in[idx] + res;
    }
    __syncthreads();
    // reset state for the next graph replay
    for (int t = tid; t < 3 * NTOT; t += BLKT) g_hist[t] = 0;
    if (tid == 0) g_done = 0u;
}

extern "C" void kernel_launch(void* const* d_in, const int* in_sizes, int n_in,
                              void* d_out, int out_size)
{
    const float* pos0  = (const float*)d_in[0];
    const float* pos1  = (const float*)d_in[1];
    const float* count = (const float*)d_in[2];
    const float* rs    = (const float*)d_in[3];
    int n0 = in_sizes[0] / 3;
    int n1 = in_sizes[1] / 3;
    float* out = (float*)d_out;

    sort_kernel<<<2, SORTT>>>(pos0, pos1, rs, n0, n1);

    int nb0 = (n0 + TILE - 1) / TILE;
    int nb1 = (n1 + TILE - 1) / TILE;
    int T0 = nb0 * (nb0 + 1) / 2;
    int C  = nb0 * nb1;
    int T1 = nb1 * (nb1 + 1) / 2;
    pair_fused_kernel<<<T0 + C + T1, BLKT>>>(count, out, rs, n0, n1,
                                             nb0, nb1, T0, C);
}

// round 7
// speedup vs baseline: 1.1713x; 1.1713x over previous
#include <cuda_runtime.h>

#define NTOT 200      // histogram bins
#define TILEA 256     // A rows per block
#define TILEB 128     // B cols per block (half-tile -> 2x grid, 16 blocks/SM)
#define BLKT 128      // threads per block (2 A rows per thread)
#define NWARP 4
#define NBUCK 256     // x-sort buckets
#define SORTT 1024    // sort-kernel threads
#define MAXPTS 16384

// Sorted & prescaled points: (x,y,z)*real_size*20, w=|p|^2.
__device__ float4 g_pts[MAXPTS];
// 3 raw integer histograms: [0]=00-tri, [1]=01-cross, [2]=11-tri.
// finalize_kernel re-zeroes after reading -> graph replays start clean.
__device__ int g_hist[3 * NTOT];

__device__ __forceinline__ float fsqrt_approx(float x) {
    float r;
    asm("sqrt.approx.f32 %0, %1;" : "=f"(r) : "f"(x));
    return r;
}

// Counting sort by x-bucket; block 0 -> pos0, block 1 -> pos1. Within-bucket
// order is race-dependent, which is fine: the histogram is a permutation-
// invariant integer reduction.
__global__ __launch_bounds__(SORTT) void sort_kernel(
    const float* __restrict__ pos0, const float* __restrict__ pos1,
    const float* __restrict__ rs, int n0, int n1)
{
    __shared__ int cnt[NBUCK];
    __shared__ int offs[NBUCK];
    const float* p = blockIdx.x ? pos1 : pos0;
    const int n    = blockIdx.x ? n1 : n0;
    const int base = blockIdx.x ? n0 : 0;
    const int tid  = threadIdx.x;

    const float r0 = rs[0] * 20.0f, r1 = rs[1] * 20.0f, r2 = rs[2] * 20.0f;

    if (tid < NBUCK) cnt[tid] = 0;
    __syncthreads();
    for (int i = tid; i < n; i += SORTT) {
        int b = (int)(p[3 * i] * (float)NBUCK);
        b = max(0, min(NBUCK - 1, b));
        atomicAdd(&cnt[b], 1);
    }
    __syncthreads();
    int own = (tid < NBUCK) ? cnt[tid] : 0;
    for (int d = 1; d < NBUCK; d <<= 1) {
        int t = 0;
        if (tid < NBUCK && tid >= d) t = cnt[tid - d];
        __syncthreads();
        if (tid < NBUCK) cnt[tid] += t;
        __syncthreads();
    }
    if (tid < NBUCK) offs[tid] = cnt[tid] - own;   // exclusive start cursor
    __syncthreads();
    for (int i = tid; i < n; i += SORTT) {
        float x = p[3 * i + 0];
        float y = p[3 * i + 1];
        float z = p[3 * i + 2];
        int b = (int)(x * (float)NBUCK);
        b = max(0, min(NBUCK - 1, b));
        int pos = atomicAdd(&offs[b], 1);
        float sx = x * r0, sy = y * r1, sz = z * r2;
        float q = sx * sx; q = fmaf(sy, sy, q); q = fmaf(sz, sz, q);
        g_pts[base + pos] = make_float4(sx, sy, sz, q);
    }
}

// Invert upper-triangle linear index t -> (bi, bj), bj >= bi.
__device__ __forceinline__ void tri_decode(int t, int n, int& bi, int& bj) {
    float fn = (float)(2 * n + 1);
    int b = (int)((fn - sqrtf(fmaxf(fn * fn - 8.0f * (float)t, 0.0f))) * 0.5f);
    if (b < 0) b = 0;
    if (b > n - 1) b = n - 1;
    while (b > 0 && t < b * (2 * n - b + 1) / 2) b--;
    while (b < n - 1 && t >= (b + 1) * (2 * n - b) / 2) b++;
    bi = b;
    bj = b + (t - b * (2 * n - b + 1) / 2);
}

// All three pair regions in one grid. Each 256x256 logical tile is split into
// two 256x128 blocks (bit 0 of blockIdx selects the B half) so ~16 blocks fit
// per SM instead of ~8.
__global__ __launch_bounds__(BLKT, 16) void pair_fused_kernel(
    int n0, int n1, int nb0, int nb1, int T0, int C)
{
    __shared__ float4 sB[TILEB];
    __shared__ int    sh[NWARP * NTOT];

    // ---- decode block -> (tile, B-half) ----
    int w    = blockIdx.x >> 1;
    int half = blockIdx.x & 1;
    int bi, bj, aOff, bOff, nA, nB, histIdx;
    bool diag;
    if (w < T0) {                     // 0-0 triangle
        tri_decode(w, nb0, bi, bj);
        aOff = 0; bOff = 0; nA = n0; nB = n0; histIdx = 0;
        diag = (bi == bj);
    } else if (w < T0 + C) {          // 0-1 cross
        int u = w - T0;
        bi = u / nb1; bj = u - bi * nb1;
        aOff = 0; nA = n0; bOff = n0; nB = n1; histIdx = 1;
        diag = false;
    } else {                          // 1-1 triangle
        int u = w - T0 - C;
        tri_decode(u, nb1, bi, bj);
        aOff = n0; bOff = n0; nA = n1; nB = n1; histIdx = 2;
        diag = (bi == bj);
    }
    const int rowStart  = bi * TILEA;
    const int chunkBase = bj * TILEA + half * TILEB;
    if (chunkBase >= nB) return;

    // ---- x-gap cull (bucket-granular sort: pad cutoff 200 -> 205) ----
    {
        float a_lo = g_pts[aOff + rowStart].x;
        float a_hi = g_pts[aOff + min(rowStart + TILEA - 1, nA - 1)].x;
        float b_lo = g_pts[bOff + chunkBase].x;
        float b_hi = g_pts[bOff + min(chunkBase + TILEB - 1, nB - 1)].x;
        if (fmaxf(b_lo - a_hi, a_lo - b_hi) > 205.0f) return;
    }

    const int tid = threadIdx.x;
    const int wid = tid >> 5;
    int* myh = &sh[wid * NTOT];

    #pragma unroll
    for (int idx = tid; idx < NWARP * NTOT; idx += BLKT) sh[idx] = 0;

    {
        int j = chunkBase + tid;
        sB[tid] = (j < nB) ? g_pts[bOff + j]
                           : make_float4(0.f, 0.f, 0.f, 1e30f);
    }

    float ax2[2], ay2[2], az2[2], aw[2];
    int   irow[2];
    #pragma unroll
    for (int t = 0; t < 2; t++) {
        int i = rowStart + tid + t * BLKT;
        irow[t] = i;
        float4 a = (i < nA) ? g_pts[aOff + i]
                            : make_float4(0.f, 0.f, 0.f, 1e30f);
        ax2[t] = -2.0f * a.x; ay2[t] = -2.0f * a.y;
        az2[t] = -2.0f * a.z; aw[t]  = a.w;
    }
    __syncthreads();

    if (diag) {
        #pragma unroll 4
        for (int k = 0; k < TILEB; k++) {
            float4 b = sB[k];
            #pragma unroll
            for (int t = 0; t < 2; t++) {
                float s = aw[t] + b.w;
                s = fmaf(ax2[t], b.x, s);
                s = fmaf(ay2[t], b.y, s);
                s = fmaf(az2[t], b.z, s);
                float d = fsqrt_approx(fmaxf(s, 0.0f));
                if (d < (float)NTOT && (chunkBase + k) > irow[t])
                    atomicAdd(&myh[(int)d], 1);
            }
        }
    } else {
        #pragma unroll 4
        for (int k = 0; k < TILEB; k++) {
            float4 b = sB[k];
            #pragma unroll
            for (int t = 0; t < 2; t++) {
                float s = aw[t] + b.w;
                s = fmaf(ax2[t], b.x, s);
                s = fmaf(ay2[t], b.y, s);
                s = fmaf(az2[t], b.z, s);
                float d = fsqrt_approx(fmaxf(s, 0.0f));
                if (d < (float)NTOT)
                    atomicAdd(&myh[(int)d], 1);
            }
        }
    }
    __syncthreads();

    for (int t = tid; t < NTOT; t += BLKT) {
        int v = sh[t] + sh[NTOT + t] + sh[2 * NTOT + t] + sh[3 * NTOT + t];
        if (v) atomicAdd(&g_hist[histIdx * NTOT + t], v);
    }
}

// Single block: normalize all 800 outputs, then zero g_hist for next replay.
__global__ void finalize_kernel(const float* __restrict__ count_in,
                                float* __restrict__ out,
                                const float* __restrict__ rs,
                                int n0, int n1)
{
    int idx = threadIdx.x;
    if (idx < 4 * NTOT) {
        int k  = idx % NTOT;
        int ij = idx / NTOT;                       // i*2 + j
        int histIdx = (ij == 0) ? 0 : ((ij == 3) ? 2 : 1);
        float mult  = (ij == 0 || ij == 3) ? 2.0f : 1.0f;  // triangle -> full
        float na = (float)((ij >> 1) ? n1 : n0);
        float nb = (float)((ij & 1) ? n1 : n0);
        float vol = rs[0] * rs[1] * rs[2];

        float counts = (float)g_hist[histIdx * NTOT + k] * mult;
        double r = 0.025 + (double)k * 0.05;
        float sv = (float)(r * 0.05 * 2.0 * 3.14159265358979323846 * 3.0);
        float density = nb / vol;
        float res = counts / density / sv / na;   // same division order as ref
        out[idx] = count_in[idx] + res;
    }
    __syncthreads();
    if (idx < 3 * NTOT) g_hist[idx] = 0;
}

extern "C" void kernel_launch(void* const* d_in, const int* in_sizes, int n_in,
                              void* d_out, int out_size)
{
    const float* pos0  = (const float*)d_in[0];
    const float* pos1  = (const float*)d_in[1];
    const float* count = (const float*)d_in[2];
    const float* rs    = (const float*)d_in[3];
    int n0 = in_sizes[0] / 3;
    int n1 = in_sizes[1] / 3;
    float* out = (float*)d_out;

    sort_kernel<<<2, SORTT>>>(pos0, pos1, rs, n0, n1);

    int nb0 = (n0 + TILEA - 1) / TILEA;
    int nb1 = (n1 + TILEA - 1) / TILEA;
    int T0 = nb0 * (nb0 + 1) / 2;
    int C  = nb0 * nb1;
    int T1 = nb1 * (nb1 + 1) / 2;
    pair_fused_kernel<<<2 * (T0 + C + T1), BLKT>>>(n0, n1, nb0, nb1, T0, C);

    finalize_kernel<<<1, 4 * NTOT>>>(count, out, rs, n0, n1);
}

// round 8
// speedup vs baseline: 1.3687x; 1.1686x over previous
#include <cuda_runtime.h>

#define NTOT 200      // histogram bins
#define TILEA 256     // A rows per block
#define TILEB 64      // B cols per block (quarter-tile -> 2 waves, steal-balanced)
#define BLKT 128      // threads per block (2 A rows per thread)
#define NWARP 4
#define NBUCK 256     // x-sort buckets
#define SORTT 1024    // sort-kernel threads
#define MAXPTS 16384
#define PPT 8         // max points per sort thread

// Sorted & prescaled points: (x,y,z)*real_size*20, w=|p|^2.
__device__ float4 g_pts[MAXPTS];
// 3 raw integer histograms: [0]=00-tri, [1]=01-cross, [2]=11-tri.
// finalize_kernel re-zeroes after reading -> graph replays start clean.
__device__ int g_hist[3 * NTOT];

__device__ __forceinline__ float fsqrt_approx(float x) {
    float r;
    asm("sqrt.approx.f32 %0, %1;" : "=f"(r) : "f"(x));
    return r;
}

// Counting sort by x-bucket; block 0 -> pos0, block 1 -> pos1.
// Points stay in registers between the count and scatter phases (one global
// read per point), and the 256-bucket scan is a single-warp shuffle scan.
// Within-bucket order is race-dependent, which is fine: the histogram is a
// permutation-invariant integer reduction.
__global__ __launch_bounds__(SORTT) void sort_kernel(
    const float* __restrict__ pos0, const float* __restrict__ pos1,
    const float* __restrict__ rs, int n0, int n1)
{
    __shared__ int cnt[NBUCK];   // counts -> exclusive-offset cursors
    const float* p = blockIdx.x ? pos1 : pos0;
    const int n    = blockIdx.x ? n1 : n0;
    const int base = blockIdx.x ? n0 : 0;
    const int tid  = threadIdx.x;

    const float r0 = rs[0] * 20.0f, r1 = rs[1] * 20.0f, r2 = rs[2] * 20.0f;

    if (tid < NBUCK) cnt[tid] = 0;
    __syncthreads();

    float lx[PPT], ly[PPT], lz[PPT];
    int   lb[PPT];
    #pragma unroll
    for (int k = 0; k < PPT; k++) {
        int i = tid + k * SORTT;
        lb[k] = -1;
        if (i < n) {
            lx[k] = p[3 * i + 0];
            ly[k] = p[3 * i + 1];
            lz[k] = p[3 * i + 2];
            int b = (int)(lx[k] * (float)NBUCK);
            b = max(0, min(NBUCK - 1, b));
            lb[k] = b;
            atomicAdd(&cnt[b], 1);
        }
    }
    __syncthreads();

    // Single-warp scan: lane L owns buckets [8L, 8L+8).
    if (tid < 32) {
        int v[8], s = 0;
        #pragma unroll
        for (int j = 0; j < 8; j++) { v[j] = cnt[tid * 8 + j]; s += v[j]; }
        int e = s;
        #pragma unroll
        for (int d = 1; d < 32; d <<= 1) {
            int t = __shfl_up_sync(0xFFFFFFFFu, e, d);
            if (tid >= d) e += t;
        }
        e -= s;   // exclusive prefix of this lane's 8-bucket group
        #pragma unroll
        for (int j = 0; j < 8; j++) { int t = v[j]; cnt[tid * 8 + j] = e; e += t; }
    }
    __syncthreads();

    #pragma unroll
    for (int k = 0; k < PPT; k++) {
        if (lb[k] >= 0) {
            int pos = atomicAdd(&cnt[lb[k]], 1);
            float sx = lx[k] * r0, sy = ly[k] * r1, sz = lz[k] * r2;
            float q = sx * sx; q = fmaf(sy, sy, q); q = fmaf(sz, sz, q);
            g_pts[base + pos] = make_float4(sx, sy, sz, q);
        }
    }
}

// Invert upper-triangle linear index t -> (bi, bj), bj >= bi.
__device__ __forceinline__ void tri_decode(int t, int n, int& bi, int& bj) {
    float fn = (float)(2 * n + 1);
    int b = (int)((fn - sqrtf(fmaxf(fn * fn - 8.0f * (float)t, 0.0f))) * 0.5f);
    if (b < 0) b = 0;
    if (b > n - 1) b = n - 1;
    while (b > 0 && t < b * (2 * n - b + 1) / 2) b--;
    while (b < n - 1 && t >= (b + 1) * (2 * n - b) / 2) b++;
    bi = b;
    bj = b + (t - b * (2 * n - b + 1) / 2);
}

// All three pair regions in one grid. Each 256x256 logical tile is split into
// four 256x64 blocks (low 2 bits of blockIdx select the B quarter) -> ~2
// waves of 16 blocks/SM, so early-exiting culled/empty blocks are backfilled
// by wave-2 work instead of leaving SM slots idle.
__global__ __launch_bounds__(BLKT, 16) void pair_fused_kernel(
    int n0, int n1, int nb0, int nb1, int T0, int C)
{
    __shared__ float4 sB[TILEB];
    __shared__ int    sh[NWARP * NTOT];

    // ---- decode block -> (tile, B-quarter) ----
    int w    = blockIdx.x >> 2;
    int quar = blockIdx.x & 3;
    int bi, bj, aOff, bOff, nA, nB, histIdx;
    bool diag;
    if (w < T0) {                     // 0-0 triangle
        tri_decode(w, nb0, bi, bj);
        aOff = 0; bOff = 0; nA = n0; nB = n0; histIdx = 0;
        diag = (bi == bj);
    } else if (w < T0 + C) {          // 0-1 cross
        int u = w - T0;
        bi = u / nb1; bj = u - bi * nb1;
        aOff = 0; nA = n0; bOff = n0; nB = n1; histIdx = 1;
        diag = false;
    } else {                          // 1-1 triangle
        int u = w - T0 - C;
        tri_decode(u, nb1, bi, bj);
        aOff = n0; bOff = n0; nA = n1; nB = n1; histIdx = 2;
        diag = (bi == bj);
    }
    const int rowStart  = bi * TILEA;
    const int chunkBase = bj * TILEA + quar * TILEB;
    if (chunkBase >= nB) return;

    // ---- x-gap cull (bucket-granular sort: pad cutoff 200 -> 205) ----
    {
        float a_lo = g_pts[aOff + rowStart].x;
        float a_hi = g_pts[aOff + min(rowStart + TILEA - 1, nA - 1)].x;
        float b_lo = g_pts[bOff + chunkBase].x;
        float b_hi = g_pts[bOff + min(chunkBase + TILEB - 1, nB - 1)].x;
        if (fmaxf(b_lo - a_hi, a_lo - b_hi) > 205.0f) return;
    }

    const int tid = threadIdx.x;
    const int wid = tid >> 5;
    int* myh = &sh[wid * NTOT];

    #pragma unroll
    for (int idx = tid; idx < NWARP * NTOT; idx += BLKT) sh[idx] = 0;

    if (tid < TILEB) {
        int j = chunkBase + tid;
        sB[tid] = (j < nB) ? g_pts[bOff + j]
                           : make_float4(0.f, 0.f, 0.f, 1e30f);
    }

    float ax2[2], ay2[2], az2[2], aw[2];
    int   irow[2];
    #pragma unroll
    for (int t = 0; t < 2; t++) {
        int i = rowStart + tid + t * BLKT;
        irow[t] = i;
        float4 a = (i < nA) ? g_pts[aOff + i]
                            : make_float4(0.f, 0.f, 0.f, 1e30f);
        ax2[t] = -2.0f * a.x; ay2[t] = -2.0f * a.y;
        az2[t] = -2.0f * a.z; aw[t]  = a.w;
    }
    __syncthreads();

    if (diag) {
        #pragma unroll 4
        for (int k = 0; k < TILEB; k++) {
            float4 b = sB[k];
            #pragma unroll
            for (int t = 0; t < 2; t++) {
                float s = aw[t] + b.w;
                s = fmaf(ax2[t], b.x, s);
                s = fmaf(ay2[t], b.y, s);
                s = fmaf(az2[t], b.z, s);
                float d = fsqrt_approx(fmaxf(s, 0.0f));
                if (d < (float)NTOT && (chunkBase + k) > irow[t])
                    atomicAdd(&myh[(int)d], 1);
            }
        }
    } else {
        #pragma unroll 4
        for (int k = 0; k < TILEB; k++) {
            float4 b = sB[k];
            #pragma unroll
            for (int t = 0; t < 2; t++) {
                float s = aw[t] + b.w;
                s = fmaf(ax2[t], b.x, s);
                s = fmaf(ay2[t], b.y, s);
                s = fmaf(az2[t], b.z, s);
                float d = fsqrt_approx(fmaxf(s, 0.0f));
                if (d < (float)NTOT)
                    atomicAdd(&myh[(int)d], 1);
            }
        }
    }
    __syncthreads();

    for (int t = tid; t < NTOT; t += BLKT) {
        int v = sh[t] + sh[NTOT + t] + sh[2 * NTOT + t] + sh[3 * NTOT + t];
        if (v) atomicAdd(&g_hist[histIdx * NTOT + t], v);
    }
}

// Single block: normalize all 800 outputs, then zero g_hist for next replay.
__global__ void finalize_kernel(const float* __restrict__ count_in,
                                float* __restrict__ out,
                                const float* __restrict__ rs,
                                int n0, int n1)
{
    int idx = threadIdx.x;
    if (idx < 4 * NTOT) {
        int k  = idx % NTOT;
        int ij = idx / NTOT;                       // i*2 + j
        int histIdx = (ij == 0) ? 0 : ((ij == 3) ? 2 : 1);
        float mult  = (ij == 0 || ij == 3) ? 2.0f : 1.0f;  // triangle -> full
        float na = (float)((ij >> 1) ? n1 : n0);
        float nb = (float)((ij & 1) ? n1 : n0);
        float vol = rs[0] * rs[1] * rs[2];

        float counts = (float)g_hist[histIdx * NTOT + k] * mult;
        double r = 0.025 + (double)k * 0.05;
        float sv = (float)(r * 0.05 * 2.0 * 3.14159265358979323846 * 3.0);
        float density = nb / vol;
        float res = counts / density / sv / na;   // same division order as ref
        out[idx] = count_in[idx] + res;
    }
    __syncthreads();
    if (idx < 3 * NTOT) g_hist[idx] = 0;
}

extern "C" void kernel_launch(void* const* d_in, const int* in_sizes, int n_in,
                              void* d_out, int out_size)
{
    const float* pos0  = (const float*)d_in[0];
    const float* pos1  = (const float*)d_in[1];
    const float* count = (const float*)d_in[2];
    const float* rs    = (const float*)d_in[3];
    int n0 = in_sizes[0] / 3;
    int n1 = in_sizes[1] / 3;
    float* out = (float*)d_out;

    sort_kernel<<<2, SORTT>>>(pos0, pos1, rs, n0, n1);

    int nb0 = (n0 + TILEA - 1) / TILEA;
    int nb1 = (n1 + TILEA - 1) / TILEA;
    int T0 = nb0 * (nb0 + 1) / 2;
    int C  = nb0 * nb1;
    int T1 = nb1 * (nb1 + 1) / 2;
    pair_fused_kernel<<<4 * (T0 + C + T1), BLKT>>>(n0, n1, nb0, nb1, T0, C);

    finalize_kernel<<<1, 4 * NTOT>>>(count, out, rs, n0, n1);
}

// round 9
// speedup vs baseline: 1.4256x; 1.0416x over previous
#include <cuda_runtime.h>

#define NTOT 200      // histogram bins
#define TILEA 256     // A rows per block
#define TILEB 64      // B cols per block (quarter-tile -> 2 waves, steal-balanced)
#define BLKT 128      // threads per block (2 A rows per thread)
#define NWARP 4
#define NBUCK 256     // x-sort buckets
#define GROUPS 16     // sorter blocks per array (each owns NBUCK/GROUPS buckets)
#define BPB (NBUCK / GROUPS)
#define SORTT 256     // sort-kernel threads
#define MAXPTS 16384

// Sorted & prescaled points: (x,y,z)*real_size*20, w=|p|^2.
__device__ float4 g_pts[MAXPTS];
// 3 raw integer histograms: [0]=00-tri, [1]=01-cross, [2]=11-tri.
// finalize_kernel re-zeroes after reading -> graph replays start clean.
__device__ int g_hist[3 * NTOT];

__device__ __forceinline__ float fsqrt_approx(float x) {
    float r;
    asm("sqrt.approx.f32 %0, %1;" : "=f"(r) : "f"(x));
    return r;
}

// Decentralized counting sort: 2*GROUPS blocks, no inter-block communication.
// Every block re-derives the FULL bucket count for its array (input is tiny
// and L2-broadcast), scans locally to get global offsets, then scatters only
// the buckets it owns. Within-bucket order is race-dependent, which is fine:
// the histogram is a permutation-invariant integer reduction.
__global__ __launch_bounds__(SORTT) void sort_kernel(
    const float* __restrict__ pos0, const float* __restrict__ pos1,
    const float* __restrict__ rs, int n0, int n1)
{
    __shared__ int cnt[NBUCK];
    __shared__ int cur[BPB];

    const int arr = blockIdx.x / GROUPS;       // 0 -> pos0, 1 -> pos1
    const int grp = blockIdx.x - arr * GROUPS; // bucket group
    const float* p = arr ? pos1 : pos0;
    const int n    = arr ? n1 : n0;
    const int base = arr ? n0 : 0;
    const int lo   = grp * BPB;                // owned buckets [lo, lo+BPB)
    const int tid  = threadIdx.x;

    const float r0 = rs[0] * 20.0f, r1 = rs[1] * 20.0f, r2 = rs[2] * 20.0f;

    cnt[tid] = 0;
    __syncthreads();

    // Pass 1: full bucket count.
    for (int i = tid; i < n; i += SORTT) {
        int b = (int)(p[3 * i] * (float)NBUCK);
        b = max(0, min(NBUCK - 1, b));
        atomicAdd(&cnt[b], 1);
    }
    __syncthreads();

    // Exclusive scan via single-warp shuffle (lane L owns buckets [8L,8L+8)).
    if (tid < 32) {
        int v[8], s = 0;
        #pragma unroll
        for (int j = 0; j < 8; j++) { v[j] = cnt[tid * 8 + j]; s += v[j]; }
        int e = s;
        #pragma unroll
        for (int d = 1; d < 32; d <<= 1) {
            int t = __shfl_up_sync(0xFFFFFFFFu, e, d);
            if (tid >= d) e += t;
        }
        e -= s;   // exclusive prefix of this lane's group
        #pragma unroll
        for (int j = 0; j < 8; j++) { int t = v[j]; cnt[tid * 8 + j] = e; e += t; }
    }
    __syncthreads();
    if (tid < BPB) cur[tid] = cnt[lo + tid];   // cursors for owned buckets
    __syncthreads();

    // Pass 2: scatter only points in owned buckets (input re-read hits L2).
    for (int i = tid; i < n; i += SORTT) {
        float x = p[3 * i + 0];
        int b = (int)(x * (float)NBUCK);
        b = max(0, min(NBUCK - 1, b));
        if (b >= lo && b < lo + BPB) {
            float y = p[3 * i + 1];
            float z = p[3 * i + 2];
            int pos = atomicAdd(&cur[b - lo], 1);
            float sx = x * r0, sy = y * r1, sz = z * r2;
            float q = sx * sx; q = fmaf(sy, sy, q); q = fmaf(sz, sz, q);
            g_pts[base + pos] = make_float4(sx, sy, sz, q);
        }
    }
}

// Invert upper-triangle linear index t -> (bi, bj), bj >= bi.
__device__ __forceinline__ void tri_decode(int t, int n, int& bi, int& bj) {
    float fn = (float)(2 * n + 1);
    int b = (int)((fn - sqrtf(fmaxf(fn * fn - 8.0f * (float)t, 0.0f))) * 0.5f);
    if (b < 0) b = 0;
    if (b > n - 1) b = n - 1;
    while (b > 0 && t < b * (2 * n - b + 1) / 2) b--;
    while (b < n - 1 && t >= (b + 1) * (2 * n - b) / 2) b++;
    bi = b;
    bj = b + (t - b * (2 * n - b + 1) / 2);
}

// All three pair regions in one grid. Each 256x256 logical tile is split into
// four 256x64 blocks (low 2 bits of blockIdx select the B quarter) -> ~2
// waves of 16 blocks/SM, so early-exiting culled/empty blocks are backfilled
// by wave-2 work instead of leaving SM slots idle.
__global__ __launch_bounds__(BLKT, 16) void pair_fused_kernel(
    int n0, int n1, int nb0, int nb1, int T0, int C)
{
    __shared__ float4 sB[TILEB];
    __shared__ int    sh[NWARP * NTOT];

    // ---- decode block -> (tile, B-quarter) ----
    int w    = blockIdx.x >> 2;
    int quar = blockIdx.x & 3;
    int bi, bj, aOff, bOff, nA, nB, histIdx;
    bool diag;
    if (w < T0) {                     // 0-0 triangle
        tri_decode(w, nb0, bi, bj);
        aOff = 0; bOff = 0; nA = n0; nB = n0; histIdx = 0;
        diag = (bi == bj);
    } else if (w < T0 + C) {          // 0-1 cross
        int u = w - T0;
        bi = u / nb1; bj = u - bi * nb1;
        aOff = 0; nA = n0; bOff = n0; nB = n1; histIdx = 1;
        diag = false;
    } else {                          // 1-1 triangle
        int u = w - T0 - C;
        tri_decode(u, nb1, bi, bj);
        aOff = n0; bOff = n0; nA = n1; nB = n1; histIdx = 2;
        diag = (bi == bj);
    }
    const int rowStart  = bi * TILEA;
    const int chunkBase = bj * TILEA + quar * TILEB;
    if (chunkBase >= nB) return;

    // ---- x-gap cull (bucket-granular sort: pad cutoff 200 -> 205) ----
    {
        float a_lo = g_pts[aOff + rowStart].x;
        float a_hi = g_pts[aOff + min(rowStart + TILEA - 1, nA - 1)].x;
        float b_lo = g_pts[bOff + chunkBase].x;
        float b_hi = g_pts[bOff + min(chunkBase + TILEB - 1, nB - 1)].x;
        if (fmaxf(b_lo - a_hi, a_lo - b_hi) > 205.0f) return;
    }

    const int tid = threadIdx.x;
    const int wid = tid >> 5;
    int* myh = &sh[wid * NTOT];

    #pragma unroll
    for (int idx = tid; idx < NWARP * NTOT; idx += BLKT) sh[idx] = 0;

    if (tid < TILEB) {
        int j = chunkBase + tid;
        sB[tid] = (j < nB) ? g_pts[bOff + j]
                           : make_float4(0.f, 0.f, 0.f, 1e30f);
    }

    float ax2[2], ay2[2], az2[2], aw[2];
    int   irow[2];
    #pragma unroll
    for (int t = 0; t < 2; t++) {
        int i = rowStart + tid + t * BLKT;
        irow[t] = i;
        float4 a = (i < nA) ? g_pts[aOff + i]
                            : make_float4(0.f, 0.f, 0.f, 1e30f);
        ax2[t] = -2.0f * a.x; ay2[t] = -2.0f * a.y;
        az2[t] = -2.0f * a.z; aw[t]  = a.w;
    }
    __syncthreads();

    if (diag) {
        #pragma unroll 4
        for (int k = 0; k < TILEB; k++) {
            float4 b = sB[k];
            #pragma unroll
            for (int t = 0; t < 2; t++) {
                float s = aw[t] + b.w;
                s = fmaf(ax2[t], b.x, s);
                s = fmaf(ay2[t], b.y, s);
                s = fmaf(az2[t], b.z, s);
                float d = fsqrt_approx(fmaxf(s, 0.0f));
                if (d < (float)NTOT && (chunkBase + k) > irow[t])
                    atomicAdd(&myh[(int)d], 1);
            }
        }
    } else {
        #pragma unroll 4
        for (int k = 0; k < TILEB; k++) {
            float4 b = sB[k];
            #pragma unroll
            for (int t = 0; t < 2; t++) {
                float s = aw[t] + b.w;
                s = fmaf(ax2[t], b.x, s);
                s = fmaf(ay2[t], b.y, s);
                s = fmaf(az2[t], b.z, s);
                float d = fsqrt_approx(fmaxf(s, 0.0f));
                if (d < (float)NTOT)
                    atomicAdd(&myh[(int)d], 1);
            }
        }
    }
    __syncthreads();

    for (int t = tid; t < NTOT; t += BLKT) {
        int v = sh[t] + sh[NTOT + t] + sh[2 * NTOT + t] + sh[3 * NTOT + t];
        if (v) atomicAdd(&g_hist[histIdx * NTOT + t], v);
    }
}

// Single block: normalize all 800 outputs, then zero g_hist for next replay.
__global__ void finalize_kernel(const float* __restrict__ count_in,
                                float* __restrict__ out,
                                const float* __restrict__ rs,
                                int n0, int n1)
{
    int idx = threadIdx.x;
    if (idx < 4 * NTOT) {
        int k  = idx % NTOT;
        int ij = idx / NTOT;                       // i*2 + j
        int histIdx = (ij == 0) ? 0 : ((ij == 3) ? 2 : 1);
        float mult  = (ij == 0 || ij == 3) ? 2.0f : 1.0f;  // triangle -> full
        float na = (float)((ij >> 1) ? n1 : n0);
        float nb = (float)((ij & 1) ? n1 : n0);
        float vol = rs[0] * rs[1] * rs[2];

        float counts = (float)g_hist[histIdx * NTOT + k] * mult;
        double r = 0.025 + (double)k * 0.05;
        float sv = (float)(r * 0.05 * 2.0 * 3.14159265358979323846 * 3.0);
        float density = nb / vol;
        float res = counts / density / sv / na;   // same division order as ref
        out[idx] = count_in[idx] + res;
    }
    __syncthreads();
    if (idx < 3 * NTOT) g_hist[idx] = 0;
}

extern "C" void kernel_launch(void* const* d_in, const int* in_sizes, int n_in,
                              void* d_out, int out_size)
{
    const float* pos0  = (const float*)d_in[0];
    const float* pos1  = (const float*)d_in[1];
    const float* count = (const float*)d_in[2];
    const float* rs    = (const float*)d_in[3];
    int n0 = in_sizes[0] / 3;
    int n1 = in_sizes[1] / 3;
    float* out = (float*)d_out;

    sort_kernel<<<2 * GROUPS, SORTT>>>(pos0, pos1, rs, n0, n1);

    int nb0 = (n0 + TILEA - 1) / TILEA;
    int nb1 = (n1 + TILEA - 1) / TILEA;
    int T0 = nb0 * (nb0 + 1) / 2;
    int C  = nb0 * nb1;
    int T1 = nb1 * (nb1 + 1) / 2;
    pair_fused_kernel<<<4 * (T0 + C + T1), BLKT>>>(n0, n1, nb0, nb1, T0, C);

    finalize_kernel<<<1, 4 * NTOT>>>(count, out, rs, n0, n1);
}

// round 10
// speedup vs baseline: 1.4304x; 1.0034x over previous
#include <cuda_runtime.h>

#define NTOT 200      // histogram bins
#define TILEA 256     // A rows per block
#define TILEB 64      // B cols per block (quarter-tile -> 2 waves, steal-balanced)
#define BLKT 128      // threads per block (2 A rows per thread)
#define NWARP 4
#define NBUCK 256     // x-sort buckets
#define GROUPS 16     // sorter blocks per array (each owns NBUCK/GROUPS buckets)
#define BPB (NBUCK / GROUPS)
#define SORTT 512     // sort-kernel threads
#define SBATCH 8      // x-values batched per thread (MLP)
#define MAXPTS 16384

// Sorted & prescaled points: (x,y,z)*real_size*20, w=|p|^2.
__device__ float4 g_pts[MAXPTS];
// 3 raw integer histograms: [0]=00-tri, [1]=01-cross, [2]=11-tri.
// finalize_kernel re-zeroes after reading -> graph replays start clean.
__device__ int g_hist[3 * NTOT];

__device__ __forceinline__ float fsqrt_approx(float x) {
    float r;
    asm("sqrt.approx.f32 %0, %1;" : "=f"(r) : "f"(x));
    return r;
}

// Decentralized counting sort: 2*GROUPS blocks, no inter-block communication.
// Every block re-derives the FULL bucket count for its array, scans locally,
// then scatters only the buckets it owns. Loads are manually batched (SBATCH
// independent LDGs issued before any consumer) so the loop runs at MLP=SBATCH
// instead of serializing one ~600-cycle load latency per iteration.
__global__ __launch_bounds__(SORTT) void sort_kernel(
    const float* __restrict__ pos0, const float* __restrict__ pos1,
    const float* __restrict__ rs, int n0, int n1)
{
    __shared__ int cnt[NBUCK];
    __shared__ int cur[BPB];

    const int arr = blockIdx.x / GROUPS;       // 0 -> pos0, 1 -> pos1
    const int grp = blockIdx.x - arr * GROUPS; // bucket group
    const float* p = arr ? pos1 : pos0;
    const int n    = arr ? n1 : n0;
    const int base = arr ? n0 : 0;
    const int lo   = grp * BPB;                // owned buckets [lo, lo+BPB)
    const int tid  = threadIdx.x;

    const float r0 = rs[0] * 20.0f, r1 = rs[1] * 20.0f, r2 = rs[2] * 20.0f;

    for (int t = tid; t < NBUCK; t += SORTT) cnt[t] = 0;
    __syncthreads();

    // Pass 1: full bucket count, batched x loads.
    for (int b0 = 0; b0 < n; b0 += SORTT * SBATCH) {
        float xv[SBATCH];
        bool  ok[SBATCH];
        #pragma unroll
        for (int k = 0; k < SBATCH; k++) {
            int i = b0 + tid + k * SORTT;
            ok[k] = (i < n);
            xv[k] = ok[k] ? p[3 * i] : 0.0f;
        }
        #pragma unroll
        for (int k = 0; k < SBATCH; k++) {
            if (ok[k]) {
                int b = (int)(xv[k] * (float)NBUCK);
                b = max(0, min(NBUCK - 1, b));
                atomicAdd(&cnt[b], 1);
            }
        }
    }
    __syncthreads();

    // Exclusive scan via single-warp shuffle (lane L owns buckets [8L,8L+8)).
    if (tid < 32) {
        int v[8], s = 0;
        #pragma unroll
        for (int j = 0; j < 8; j++) { v[j] = cnt[tid * 8 + j]; s += v[j]; }
        int e = s;
        #pragma unroll
        for (int d = 1; d < 32; d <<= 1) {
            int t = __shfl_up_sync(0xFFFFFFFFu, e, d);
            if (tid >= d) e += t;
        }
        e -= s;   // exclusive prefix of this lane's group
        #pragma unroll
        for (int j = 0; j < 8; j++) { int t = v[j]; cnt[tid * 8 + j] = e; e += t; }
    }
    __syncthreads();
    if (tid < BPB) cur[tid] = cnt[lo + tid];   // cursors for owned buckets
    __syncthreads();

    // Pass 2: batched x re-read (L2-hot); fetch y,z only for owned points
    // (~1/GROUPS of them), then scatter.
    for (int b0 = 0; b0 < n; b0 += SORTT * SBATCH) {
        float xv[SBATCH];
        int   bk[SBATCH];
        #pragma unroll
        for (int k = 0; k < SBATCH; k++) {
            int i = b0 + tid + k * SORTT;
            xv[k] = (i < n) ? p[3 * i] : -1.0f;
        }
        #pragma unroll
        for (int k = 0; k < SBATCH; k++) {
            int b = (int)(xv[k] * (float)NBUCK);
            bk[k] = (xv[k] < 0.0f) ? -1 : max(0, min(NBUCK - 1, b));
        }
        #pragma unroll
        for (int k = 0; k < SBATCH; k++) {
            int b = bk[k];
            if (b >= lo && b < lo + BPB) {
                int i = b0 + tid + k * SORTT;
                float y = p[3 * i + 1];
                float z = p[3 * i + 2];
                int pos = atomicAdd(&cur[b - lo], 1);
                float sx = xv[k] * r0, sy = y * r1, sz = z * r2;
                float q = sx * sx; q = fmaf(sy, sy, q); q = fmaf(sz, sz, q);
                g_pts[base + pos] = make_float4(sx, sy, sz, q);
            }
        }
    }
}

// Invert upper-triangle linear index t -> (bi, bj), bj >= bi.
__device__ __forceinline__ void tri_decode(int t, int n, int& bi, int& bj) {
    float fn = (float)(2 * n + 1);
    int b = (int)((fn - sqrtf(fmaxf(fn * fn - 8.0f * (float)t, 0.0f))) * 0.5f);
    if (b < 0) b = 0;
    if (b > n - 1) b = n - 1;
    while (b > 0 && t < b * (2 * n - b + 1) / 2) b--;
    while (b < n - 1 && t >= (b + 1) * (2 * n - b) / 2) b++;
    bi = b;
    bj = b + (t - b * (2 * n - b + 1) / 2);
}

// All three pair regions in one grid. Each 256x256 logical tile is split into
// four 256x64 blocks -> ~2 waves of 16 blocks/SM, so early-exiting culled
// blocks are backfilled by wave-2 work.
__global__ __launch_bounds__(BLKT, 16) void pair_fused_kernel(
    int n0, int n1, int nb0, int nb1, int T0, int C)
{
    __shared__ float4 sB[TILEB];
    __shared__ int    sh[NWARP * NTOT];

    // ---- decode block -> (tile, B-quarter) ----
    int w    = blockIdx.x >> 2;
    int quar = blockIdx.x & 3;
    int bi, bj, aOff, bOff, nA, nB, histIdx;
    bool diag;
    if (w < T0) {                     // 0-0 triangle
        tri_decode(w, nb0, bi, bj);
        aOff = 0; bOff = 0; nA = n0; nB = n0; histIdx = 0;
        diag = (bi == bj);
    } else if (w < T0 + C) {          // 0-1 cross
        int u = w - T0;
        bi = u / nb1; bj = u - bi * nb1;
        aOff = 0; nA = n0; bOff = n0; nB = n1; histIdx = 1;
        diag = false;
    } else {                          // 1-1 triangle
        int u = w - T0 - C;
        tri_decode(u, nb1, bi, bj);
        aOff = n0; bOff = n0; nA = n1; nB = n1; histIdx = 2;
        diag = (bi == bj);
    }
    const int rowStart  = bi * TILEA;
    const int chunkBase = bj * TILEA + quar * TILEB;
    if (chunkBase >= nB) return;

    // ---- x-gap cull (bucket-granular sort: pad cutoff 200 -> 205) ----
    {
        float a_lo = g_pts[aOff + rowStart].x;
        float a_hi = g_pts[aOff + min(rowStart + TILEA - 1, nA - 1)].x;
        float b_lo = g_pts[bOff + chunkBase].x;
        float b_hi = g_pts[bOff + min(chunkBase + TILEB - 1, nB - 1)].x;
        if (fmaxf(b_lo - a_hi, a_lo - b_hi) > 205.0f) return;
    }

    const int tid = threadIdx.x;
    const int wid = tid >> 5;
    int* myh = &sh[wid * NTOT];

    #pragma unroll
    for (int idx = tid; idx < NWARP * NTOT; idx += BLKT) sh[idx] = 0;

    if (tid < TILEB) {
        int j = chunkBase + tid;
        sB[tid] = (j < nB) ? g_pts[bOff + j]
                           : make_float4(0.f, 0.f, 0.f, 1e30f);
    }

    float ax2[2], ay2[2], az2[2], aw[2];
    int   irow[2];
    #pragma unroll
    for (int t = 0; t < 2; t++) {
        int i = rowStart + tid + t * BLKT;
        irow[t] = i;
        float4 a = (i < nA) ? g_pts[aOff + i]
                            : make_float4(0.f, 0.f, 0.f, 1e30f);
        ax2[t] = -2.0f * a.x; ay2[t] = -2.0f * a.y;
        az2[t] = -2.0f * a.z; aw[t]  = a.w;
    }
    __syncthreads();

    if (diag) {
        #pragma unroll 4
        for (int k = 0; k < TILEB; k++) {
            float4 b = sB[k];
            #pragma unroll
            for (int t = 0; t < 2; t++) {
                float s = aw[t] + b.w;
                s = fmaf(ax2[t], b.x, s);
                s = fmaf(ay2[t], b.y, s);
                s = fmaf(az2[t], b.z, s);
                float d = fsqrt_approx(fmaxf(s, 0.0f));
                if (d < (float)NTOT && (chunkBase + k) > irow[t])
                    atomicAdd(&myh[(int)d], 1);
            }
        }
    } else {
        #pragma unroll 4
        for (int k = 0; k < TILEB; k++) {
            float4 b = sB[k];
            #pragma unroll
            for (int t = 0; t < 2; t++) {
                float s = aw[t] + b.w;
                s = fmaf(ax2[t], b.x, s);
                s = fmaf(ay2[t], b.y, s);
                s = fmaf(az2[t], b.z, s);
                float d = fsqrt_approx(fmaxf(s, 0.0f));
                if (d < (float)NTOT)
                    atomicAdd(&myh[(int)d], 1);
            }
        }
    }
    __syncthreads();

    for (int t = tid; t < NTOT; t += BLKT) {
        int v = sh[t] + sh[NTOT + t] + sh[2 * NTOT + t] + sh[3 * NTOT + t];
        if (v) atomicAdd(&g_hist[histIdx * NTOT + t], v);
    }
}

// Single block: normalize all 800 outputs, then zero g_hist for next replay.
__global__ void finalize_kernel(const float* __restrict__ count_in,
                                float* __restrict__ out,
                                const float* __restrict__ rs,
                                int n0, int n1)
{
    int idx = threadIdx.x;
    if (idx < 4 * NTOT) {
        int k  = idx % NTOT;
        int ij = idx / NTOT;                       // i*2 + j
        int histIdx = (ij == 0) ? 0 : ((ij == 3) ? 2 : 1);
        float mult  = (ij == 0 || ij == 3) ? 2.0f : 1.0f;  // triangle -> full
        float na = (float)((ij >> 1) ? n1 : n0);
        float nb = (float)((ij & 1) ? n1 : n0);
        float vol = rs[0] * rs[1] * rs[2];

        float counts = (float)g_hist[histIdx * NTOT + k] * mult;
        double r = 0.025 + (double)k * 0.05;
        float sv = (float)(r * 0.05 * 2.0 * 3.14159265358979323846 * 3.0);
        float density = nb / vol;
        float res = counts / density / sv / na;   // same division order as ref
        out[idx] = count_in[idx] + res;
    }
    __syncthreads();
    if (idx < 3 * NTOT) g_hist[idx] = 0;
}

extern "C" void kernel_launch(void* const* d_in, const int* in_sizes, int n_in,
                              void* d_out, int out_size)
{
    const float* pos0  = (const float*)d_in[0];
    const float* pos1  = (const float*)d_in[1];
    const float* count = (const float*)d_in[2];
    const float* rs    = (const float*)d_in[3];
    int n0 = in_sizes[0] / 3;
    int n1 = in_sizes[1] / 3;
    float* out = (float*)d_out;

    sort_kernel<<<2 * GROUPS, SORTT>>>(pos0, pos1, rs, n0, n1);

    int nb0 = (n0 + TILEA - 1) / TILEA;
    int nb1 = (n1 + TILEA - 1) / TILEA;
    int T0 = nb0 * (nb0 + 1) / 2;
    int C  = nb0 * nb1;
    int T1 = nb1 * (nb1 + 1) / 2;
    pair_fused_kernel<<<4 * (T0 + C + T1), BLKT>>>(n0, n1, nb0, nb1, T0, C);

    finalize_kernel<<<1, 4 * NTOT>>>(count, out, rs, n0, n1);
}